// round 3
// baseline (speedup 1.0000x reference)
#include <cuda_runtime.h>
#include <math.h>
#include <stdint.h>

#define MAXN 100000
#define MAXE 1600000
#define NHID 32
#define NHEADS 8
#define DCAT 256   /* NHEADS*NHID */
#define NFEAT 128

// ---------------- scratch (device globals; no allocation allowed) ----------------
// g_h1 is reused for layer-2's h (= x2 @ W_out): agg1 fully consumes layer-1 h
// before the layer-2 GEMM runs (stream-ordered), so the buffers can alias.
__device__ float g_h1[(size_t)MAXN * DCAT];   // layer1 h, then layer2 h
__device__ float g_x2[(size_t)MAXN * DCAT];   // layer1 output (post elu)
__device__ float g_s1[MAXN * NHEADS];
__device__ float g_s2[MAXN * NHEADS];
__device__ float g_s1o[MAXN];
__device__ float g_s2o[MAXN];
__device__ float g_Wcat[NFEAT * DCAT];        // packed [128,256]
__device__ int   g_rowptr[MAXN + 1];
__device__ int   g_cursor[MAXN];
__device__ int   g_col[MAXE];
__device__ int   g_partials[128];
__device__ int   g_poff[128];

// ---------------- small helpers ----------------
__device__ __forceinline__ float warp_sum(float v) {
    #pragma unroll
    for (int o = 16; o; o >>= 1) v += __shfl_xor_sync(0xffffffffu, v, o);
    return v;
}

__device__ __forceinline__ float elu1(float v) {
    return v > 0.0f ? v : expm1f(v);
}

// ---------------- CSR build ----------------
__global__ void zero_k(int n) {
    int i = blockIdx.x * blockDim.x + threadIdx.x;
    if (i < n) g_cursor[i] = 0;
}

__global__ void pack_w(const float* __restrict__ W_heads) {
    // W_heads [8,128,32] -> Wcat [128, 256] where Wcat[k][32h+c] = W_heads[h][k][c]
    int idx = blockIdx.x * blockDim.x + threadIdx.x;
    if (idx < NHEADS * NFEAT * NHID) {
        int h = idx / (NFEAT * NHID);
        int r = (idx / NHID) % NFEAT;
        int c = idx % NHID;
        g_Wcat[r * DCAT + h * NHID + c] = W_heads[idx];
    }
}

__global__ void count_k(const int* __restrict__ src, int E) {
    int e = blockIdx.x * blockDim.x + threadIdx.x;
    if (e < E) atomicAdd(&g_cursor[src[e]], 1);
}

__global__ void scan_block(int n) {
    __shared__ int sh[1024];
    int gid = blockIdx.x * 1024 + threadIdx.x;
    int v = (gid < n) ? g_cursor[gid] : 0;
    sh[threadIdx.x] = v;
    __syncthreads();
    #pragma unroll
    for (int off = 1; off < 1024; off <<= 1) {
        int t = 0;
        if (threadIdx.x >= off) t = sh[threadIdx.x - off];
        __syncthreads();
        if (threadIdx.x >= off) sh[threadIdx.x] += t;
        __syncthreads();
    }
    if (gid < n) g_rowptr[gid] = sh[threadIdx.x] - v;   // exclusive within block
    if (threadIdx.x == 1023) g_partials[blockIdx.x] = sh[1023];
}

__global__ void scan_part(int nb, int n) {
    if (threadIdx.x == 0 && blockIdx.x == 0) {
        int acc = 0;
        for (int b = 0; b < nb; b++) { g_poff[b] = acc; acc += g_partials[b]; }
        g_rowptr[n] = acc;
    }
}

__global__ void scan_add(int n) {
    int gid = blockIdx.x * blockDim.x + threadIdx.x;
    if (gid < n) {
        int v = g_rowptr[gid] + g_poff[gid >> 10];
        g_rowptr[gid] = v;
        g_cursor[gid] = v;
    }
}

__global__ void scatter_k(const int* __restrict__ src, const int* __restrict__ dst, int E) {
    int e = blockIdx.x * blockDim.x + threadIdx.x;
    if (e < E) {
        int p = atomicAdd(&g_cursor[src[e]], 1);
        g_col[p] = dst[e];
    }
}

// ---------------- SGEMM: C[M,N] = A[M,K] @ B[K,N], N multiple of 128, K multiple of 16 ----------------
__global__ void sgemm128(const float* __restrict__ A, const float* __restrict__ B,
                         float* __restrict__ C, int M, int N, int K) {
    __shared__ float As[16][132];
    __shared__ float Bs[16][132];
    const int tid = threadIdx.x;
    const int tx = tid & 15, ty = tid >> 4;
    const int rowBase = blockIdx.y * 128;
    const int colBase = blockIdx.x * 128;
    float acc[8][8];
    #pragma unroll
    for (int i = 0; i < 8; i++)
        #pragma unroll
        for (int j = 0; j < 8; j++) acc[i][j] = 0.0f;

    for (int k0 = 0; k0 < K; k0 += 16) {
        #pragma unroll
        for (int i = 0; i < 2; i++) {
            int f = tid * 2 + i;          // 0..511
            int r = f >> 2;               // 0..127
            int c4 = (f & 3) * 4;
            float4 v = make_float4(0.f, 0.f, 0.f, 0.f);
            int gr = rowBase + r;
            if (gr < M) v = *(const float4*)(A + (size_t)gr * K + k0 + c4);
            As[c4 + 0][r] = v.x; As[c4 + 1][r] = v.y;
            As[c4 + 2][r] = v.z; As[c4 + 3][r] = v.w;

            int br = f >> 5;              // 0..15
            int bc4 = (f & 31) * 4;
            float4 w = *(const float4*)(B + (size_t)(k0 + br) * N + colBase + bc4);
            *(float4*)&Bs[br][bc4] = w;
        }
        __syncthreads();
        #pragma unroll
        for (int kk = 0; kk < 16; kk++) {
            float4 a0 = *(const float4*)&As[kk][ty * 8];
            float4 a1 = *(const float4*)&As[kk][ty * 8 + 4];
            float4 b0 = *(const float4*)&Bs[kk][tx * 8];
            float4 b1 = *(const float4*)&Bs[kk][tx * 8 + 4];
            float a[8] = {a0.x, a0.y, a0.z, a0.w, a1.x, a1.y, a1.z, a1.w};
            float b[8] = {b0.x, b0.y, b0.z, b0.w, b1.x, b1.y, b1.z, b1.w};
            #pragma unroll
            for (int i = 0; i < 8; i++)
                #pragma unroll
                for (int j = 0; j < 8; j++)
                    acc[i][j] = fmaf(a[i], b[j], acc[i][j]);
        }
        __syncthreads();
    }
    #pragma unroll
    for (int i = 0; i < 8; i++) {
        int gr = rowBase + ty * 8 + i;
        if (gr < M) {
            float4 o0 = make_float4(acc[i][0], acc[i][1], acc[i][2], acc[i][3]);
            float4 o1 = make_float4(acc[i][4], acc[i][5], acc[i][6], acc[i][7]);
            *(float4*)(C + (size_t)gr * N + colBase + tx * 8)     = o0;
            *(float4*)(C + (size_t)gr * N + colBase + tx * 8 + 4) = o1;
        }
    }
}

// ---------------- per-node scores ----------------
__global__ void score_l1(const float* __restrict__ a_heads, int n) {
    int i = (blockIdx.x * blockDim.x + threadIdx.x) >> 5;
    int lane = threadIdx.x & 31;
    if (i >= n) return;
    const float* hrow = g_h1 + (size_t)i * DCAT;
    #pragma unroll
    for (int h = 0; h < NHEADS; h++) {
        float hv = hrow[h * NHID + lane];
        float p1 = hv * a_heads[h * 64 + lane];
        float p2 = hv * a_heads[h * 64 + 32 + lane];
        p1 = warp_sum(p1);
        p2 = warp_sum(p2);
        if (lane == 0) {
            g_s1[i * NHEADS + h] = p1;
            g_s2[i * NHEADS + h] = p2;
        }
    }
}

__global__ void score_l2(const float* __restrict__ a_out, int n) {
    int i = (blockIdx.x * blockDim.x + threadIdx.x) >> 5;
    int lane = threadIdx.x & 31;
    if (i >= n) return;
    const float* hrow = g_h1 + (size_t)i * DCAT;   // layer2 h lives in g_h1
    float p1 = 0.f, p2 = 0.f;
    #pragma unroll
    for (int k = 0; k < 8; k++) {
        float hv = hrow[k * 32 + lane];
        p1 = fmaf(hv, a_out[k * 32 + lane], p1);
        p2 = fmaf(hv, a_out[256 + k * 32 + lane], p2);
    }
    p1 = warp_sum(p1);
    p2 = warp_sum(p2);
    if (lane == 0) { g_s1o[i] = p1; g_s2o[i] = p2; }
}

// ---------------- aggregation: warp per node ----------------
__global__ void agg1(int n) {
    int i = (blockIdx.x * blockDim.x + threadIdx.x) >> 5;
    int lane = threadIdx.x & 31;
    if (i >= n) return;
    float s1h = (lane < NHEADS) ? g_s1[i * NHEADS + lane] : 0.0f;
    float acc[NHEADS];
    #pragma unroll
    for (int h = 0; h < NHEADS; h++) acc[h] = 0.0f;
    float rs = 0.0f;   // lane h holds rowsum for head h (h<8)
    int pb = g_rowptr[i], pe = g_rowptr[i + 1];
    for (int p = pb; p < pe; p++) {
        int j = g_col[p];
        float eh = 0.0f;
        if (lane < NHEADS) {
            float sc = s1h + g_s2[j * NHEADS + lane];
            float t = (sc >= 0.0f) ? sc : 0.2f * sc;
            eh = __expf(-t);
            rs += eh;
        }
        const float* hr = g_h1 + (size_t)j * DCAT + lane;
        #pragma unroll
        for (int h = 0; h < NHEADS; h++) {
            float ev = __shfl_sync(0xffffffffu, eh, h);
            acc[h] = fmaf(ev, hr[h * NHID], acc[h]);
        }
    }
    float* xout = g_x2 + (size_t)i * DCAT + lane;
    #pragma unroll
    for (int h = 0; h < NHEADS; h++) {
        float r = __shfl_sync(0xffffffffu, rs, h);
        float v = acc[h] / (r + 1e-16f);
        xout[h * NHID] = elu1(v);
    }
}

__global__ void agg2(float* __restrict__ out, int n) {
    int i = (blockIdx.x * blockDim.x + threadIdx.x) >> 5;
    int lane = threadIdx.x & 31;
    if (i >= n) return;
    float s1i = g_s1o[i];
    float acc[8];
    #pragma unroll
    for (int k = 0; k < 8; k++) acc[k] = 0.0f;
    float rs = 0.0f;
    int pb = g_rowptr[i], pe = g_rowptr[i + 1];
    for (int p = pb; p < pe; p++) {
        int j = g_col[p];
        float sc = s1i + g_s2o[j];
        float t = (sc >= 0.0f) ? sc : 0.2f * sc;
        float e = __expf(-t);
        rs += e;
        const float* hr = g_h1 + (size_t)j * DCAT + lane;   // layer2 h in g_h1
        #pragma unroll
        for (int k = 0; k < 8; k++)
            acc[k] = fmaf(e, hr[k * 32], acc[k]);
    }
    float* orow = out + (size_t)i * DCAT + lane;
    float inv = 1.0f / (rs + 1e-16f);
    #pragma unroll
    for (int k = 0; k < 8; k++) {
        float v = acc[k] * inv;
        orow[k * 32] = elu1(v);
    }
}

// ---------------- launch ----------------
extern "C" void kernel_launch(void* const* d_in, const int* in_sizes, int n_in,
                              void* d_out, int out_size) {
    const float* x       = (const float*)d_in[0];
    const int*   edges   = (const int*)d_in[1];
    const float* W_heads = (const float*)d_in[2];
    const float* a_heads = (const float*)d_in[3];
    const float* W_out   = (const float*)d_in[4];
    const float* a_out   = (const float*)d_in[5];
    float* out = (float*)d_out;

    int N = in_sizes[0] / NFEAT;
    int E = in_sizes[1] / 2;
    if (N > MAXN) N = MAXN;
    if (E > MAXE) E = MAXE;
    const int* src = edges;
    const int* dst = edges + E;

    void *p_h1, *p_x2, *p_Wcat;
    cudaGetSymbolAddress(&p_h1, g_h1);
    cudaGetSymbolAddress(&p_x2, g_x2);
    cudaGetSymbolAddress(&p_Wcat, g_Wcat);

    // CSR build
    zero_k<<<(N + 255) / 256, 256>>>(N);
    pack_w<<<(NHEADS * NFEAT * NHID + 255) / 256, 256>>>(W_heads);
    count_k<<<(E + 255) / 256, 256>>>(src, E);
    int nb = (N + 1023) / 1024;
    scan_block<<<nb, 1024>>>(N);
    scan_part<<<1, 32>>>(nb, N);
    scan_add<<<(N + 255) / 256, 256>>>(N);
    scatter_k<<<(E + 255) / 256, 256>>>(src, dst, E);

    int warpBlocks = (N * 32 + 255) / 256;

    // Layer 1
    sgemm128<<<dim3(DCAT / 128, (N + 127) / 128), 256>>>(
        x, (const float*)p_Wcat, (float*)p_h1, N, DCAT, NFEAT);
    score_l1<<<warpBlocks, 256>>>(a_heads, N);
    agg1<<<warpBlocks, 256>>>(N);

    // Layer 2 (h2 reuses g_h1)
    sgemm128<<<dim3(DCAT / 128, (N + 127) / 128), 256>>>(
        (const float*)p_x2, W_out, (float*)p_h1, N, DCAT, DCAT);
    score_l2<<<warpBlocks, 256>>>(a_out, N);
    agg2<<<warpBlocks, 256>>>(out, N);
}

// round 4
// speedup vs baseline: 1.0327x; 1.0327x over previous
#include <cuda_runtime.h>
#include <math.h>
#include <stdint.h>

#define MAXN 100000
#define MAXE 1600000
#define NHID 32
#define NHEADS 8
#define DCAT 256   /* NHEADS*NHID */
#define NFEAT 128

// ---------------- scratch (device globals; no allocation allowed) ----------------
// g_h1 is reused for layer-2's h (= x2 @ W_out): agg1 fully consumes layer-1 h
// before the layer-2 GEMM runs (stream-ordered), so the buffers can alias.
__device__ float g_h1[(size_t)MAXN * DCAT];   // layer1 h, then layer2 h
__device__ float g_x2[(size_t)MAXN * DCAT];   // layer1 output (post elu)
__device__ float g_s1[MAXN * NHEADS];
__device__ float g_s2[MAXN * NHEADS];
__device__ float g_s1o[MAXN];
__device__ float g_s2o[MAXN];
__device__ float g_Wcat[NFEAT * DCAT];        // packed [128,256]
__device__ int   g_rowptr[MAXN + 1];
__device__ int   g_cursor[MAXN];
__device__ int   g_col[MAXE];
__device__ int   g_partials[128];
__device__ int   g_poff[128];

// ---------------- small helpers ----------------
__device__ __forceinline__ float warp_sum(float v) {
    #pragma unroll
    for (int o = 16; o; o >>= 1) v += __shfl_xor_sync(0xffffffffu, v, o);
    return v;
}

__device__ __forceinline__ float elu1(float v) {
    return v > 0.0f ? v : expm1f(v);
}

// ---------------- CSR build ----------------
__global__ void zero_k(int n) {
    int i = blockIdx.x * blockDim.x + threadIdx.x;
    if (i < n) g_cursor[i] = 0;
}

__global__ void pack_w(const float* __restrict__ W_heads) {
    // W_heads [8,128,32] -> Wcat [128, 256] where Wcat[k][32h+c] = W_heads[h][k][c]
    int idx = blockIdx.x * blockDim.x + threadIdx.x;
    if (idx < NHEADS * NFEAT * NHID) {
        int h = idx / (NFEAT * NHID);
        int r = (idx / NHID) % NFEAT;
        int c = idx % NHID;
        g_Wcat[r * DCAT + h * NHID + c] = W_heads[idx];
    }
}

__global__ void count_k(const int* __restrict__ src, int E) {
    int e = blockIdx.x * blockDim.x + threadIdx.x;
    if (e < E) atomicAdd(&g_cursor[src[e]], 1);
}

__global__ void scan_block(int n) {
    __shared__ int sh[1024];
    int gid = blockIdx.x * 1024 + threadIdx.x;
    int v = (gid < n) ? g_cursor[gid] : 0;
    sh[threadIdx.x] = v;
    __syncthreads();
    #pragma unroll
    for (int off = 1; off < 1024; off <<= 1) {
        int t = 0;
        if (threadIdx.x >= off) t = sh[threadIdx.x - off];
        __syncthreads();
        if (threadIdx.x >= off) sh[threadIdx.x] += t;
        __syncthreads();
    }
    if (gid < n) g_rowptr[gid] = sh[threadIdx.x] - v;   // exclusive within block
    if (threadIdx.x == 1023) g_partials[blockIdx.x] = sh[1023];
}

__global__ void scan_part(int nb, int n) {
    if (threadIdx.x == 0 && blockIdx.x == 0) {
        int acc = 0;
        for (int b = 0; b < nb; b++) { g_poff[b] = acc; acc += g_partials[b]; }
        g_rowptr[n] = acc;
    }
}

__global__ void scan_add(int n) {
    int gid = blockIdx.x * blockDim.x + threadIdx.x;
    if (gid < n) {
        int v = g_rowptr[gid] + g_poff[gid >> 10];
        g_rowptr[gid] = v;
        g_cursor[gid] = v;
    }
}

__global__ void scatter_k(const int* __restrict__ src, const int* __restrict__ dst, int E) {
    int e = blockIdx.x * blockDim.x + threadIdx.x;
    if (e < E) {
        int p = atomicAdd(&g_cursor[src[e]], 1);
        g_col[p] = dst[e];
    }
}

// ---------------- SGEMM: C[M,N] = A[M,K] @ B[K,N], N multiple of 128, K multiple of 16 ----------------
__global__ void sgemm128(const float* __restrict__ A, const float* __restrict__ B,
                         float* __restrict__ C, int M, int N, int K) {
    __shared__ float As[16][132];
    __shared__ float Bs[16][132];
    const int tid = threadIdx.x;
    const int tx = tid & 15, ty = tid >> 4;
    const int rowBase = blockIdx.y * 128;
    const int colBase = blockIdx.x * 128;
    float acc[8][8];
    #pragma unroll
    for (int i = 0; i < 8; i++)
        #pragma unroll
        for (int j = 0; j < 8; j++) acc[i][j] = 0.0f;

    for (int k0 = 0; k0 < K; k0 += 16) {
        #pragma unroll
        for (int i = 0; i < 2; i++) {
            int f = tid * 2 + i;          // 0..511
            int r = f >> 2;               // 0..127
            int c4 = (f & 3) * 4;
            float4 v = make_float4(0.f, 0.f, 0.f, 0.f);
            int gr = rowBase + r;
            if (gr < M) v = *(const float4*)(A + (size_t)gr * K + k0 + c4);
            As[c4 + 0][r] = v.x; As[c4 + 1][r] = v.y;
            As[c4 + 2][r] = v.z; As[c4 + 3][r] = v.w;

            int br = f >> 5;              // 0..15
            int bc4 = (f & 31) * 4;
            float4 w = *(const float4*)(B + (size_t)(k0 + br) * N + colBase + bc4);
            *(float4*)&Bs[br][bc4] = w;
        }
        __syncthreads();
        #pragma unroll
        for (int kk = 0; kk < 16; kk++) {
            float4 a0 = *(const float4*)&As[kk][ty * 8];
            float4 a1 = *(const float4*)&As[kk][ty * 8 + 4];
            float4 b0 = *(const float4*)&Bs[kk][tx * 8];
            float4 b1 = *(const float4*)&Bs[kk][tx * 8 + 4];
            float a[8] = {a0.x, a0.y, a0.z, a0.w, a1.x, a1.y, a1.z, a1.w};
            float b[8] = {b0.x, b0.y, b0.z, b0.w, b1.x, b1.y, b1.z, b1.w};
            #pragma unroll
            for (int i = 0; i < 8; i++)
                #pragma unroll
                for (int j = 0; j < 8; j++)
                    acc[i][j] = fmaf(a[i], b[j], acc[i][j]);
        }
        __syncthreads();
    }
    #pragma unroll
    for (int i = 0; i < 8; i++) {
        int gr = rowBase + ty * 8 + i;
        if (gr < M) {
            float4 o0 = make_float4(acc[i][0], acc[i][1], acc[i][2], acc[i][3]);
            float4 o1 = make_float4(acc[i][4], acc[i][5], acc[i][6], acc[i][7]);
            *(float4*)(C + (size_t)gr * N + colBase + tx * 8)     = o0;
            *(float4*)(C + (size_t)gr * N + colBase + tx * 8 + 4) = o1;
        }
    }
}

// ---------------- per-node scores ----------------
__global__ void score_l1(const float* __restrict__ a_heads, int n) {
    int i = (blockIdx.x * blockDim.x + threadIdx.x) >> 5;
    int lane = threadIdx.x & 31;
    if (i >= n) return;
    const float* hrow = g_h1 + (size_t)i * DCAT;
    #pragma unroll
    for (int h = 0; h < NHEADS; h++) {
        float hv = hrow[h * NHID + lane];
        float p1 = hv * a_heads[h * 64 + lane];
        float p2 = hv * a_heads[h * 64 + 32 + lane];
        p1 = warp_sum(p1);
        p2 = warp_sum(p2);
        if (lane == 0) {
            g_s1[i * NHEADS + h] = p1;
            g_s2[i * NHEADS + h] = p2;
        }
    }
}

__global__ void score_l2(const float* __restrict__ a_out, int n) {
    int i = (blockIdx.x * blockDim.x + threadIdx.x) >> 5;
    int lane = threadIdx.x & 31;
    if (i >= n) return;
    const float* hrow = g_h1 + (size_t)i * DCAT;   // layer2 h lives in g_h1
    float p1 = 0.f, p2 = 0.f;
    #pragma unroll
    for (int k = 0; k < 8; k++) {
        float hv = hrow[k * 32 + lane];
        p1 = fmaf(hv, a_out[k * 32 + lane], p1);
        p2 = fmaf(hv, a_out[256 + k * 32 + lane], p2);
    }
    p1 = warp_sum(p1);
    p2 = warp_sum(p2);
    if (lane == 0) { g_s1o[i] = p1; g_s2o[i] = p2; }
}

// ---------------- aggregation: warp per node, float4 gathers ----------------
__global__ void agg1(int n) {
    int i = (blockIdx.x * blockDim.x + threadIdx.x) >> 5;
    int lane = threadIdx.x & 31;
    if (i >= n) return;
    float s1h = (lane < NHEADS) ? g_s1[i * NHEADS + lane] : 0.0f;
    // lane l accumulates row floats [4l,4l+4) (head l>>3) and [128+4l,128+4l+4) (head 4+(l>>3))
    const int h0 = lane >> 3, h1 = 4 + (lane >> 3);
    float4 acc0 = make_float4(0.f, 0.f, 0.f, 0.f);
    float4 acc1 = make_float4(0.f, 0.f, 0.f, 0.f);
    float rs = 0.0f;   // lane h (<8) holds rowsum for head h
    int pb = g_rowptr[i], pe = g_rowptr[i + 1];
    int j = (pb < pe) ? g_col[pb] : 0;
    for (int p = pb; p < pe; p++) {
        int jn = (p + 1 < pe) ? g_col[p + 1] : 0;     // prefetch next column
        float eh = 0.0f;
        if (lane < NHEADS) {
            float sc = s1h + g_s2[j * NHEADS + lane];
            float t = (sc >= 0.0f) ? sc : 0.2f * sc;
            eh = __expf(-t);
            rs += eh;
        }
        const float4* hr = (const float4*)(g_h1 + (size_t)j * DCAT);
        float4 v0 = hr[lane];
        float4 v1 = hr[lane + 32];
        float e0 = __shfl_sync(0xffffffffu, eh, h0);
        float e1 = __shfl_sync(0xffffffffu, eh, h1);
        acc0.x = fmaf(e0, v0.x, acc0.x); acc0.y = fmaf(e0, v0.y, acc0.y);
        acc0.z = fmaf(e0, v0.z, acc0.z); acc0.w = fmaf(e0, v0.w, acc0.w);
        acc1.x = fmaf(e1, v1.x, acc1.x); acc1.y = fmaf(e1, v1.y, acc1.y);
        acc1.z = fmaf(e1, v1.z, acc1.z); acc1.w = fmaf(e1, v1.w, acc1.w);
        j = jn;
    }
    float r0 = __shfl_sync(0xffffffffu, rs, h0) + 1e-16f;
    float r1 = __shfl_sync(0xffffffffu, rs, h1) + 1e-16f;
    float inv0 = 1.0f / r0, inv1 = 1.0f / r1;
    float4 o0 = make_float4(elu1(acc0.x * inv0), elu1(acc0.y * inv0),
                            elu1(acc0.z * inv0), elu1(acc0.w * inv0));
    float4 o1 = make_float4(elu1(acc1.x * inv1), elu1(acc1.y * inv1),
                            elu1(acc1.z * inv1), elu1(acc1.w * inv1));
    float4* xout = (float4*)(g_x2 + (size_t)i * DCAT);
    xout[lane] = o0;
    xout[lane + 32] = o1;
}

__global__ void agg2(float* __restrict__ out, int n) {
    int i = (blockIdx.x * blockDim.x + threadIdx.x) >> 5;
    int lane = threadIdx.x & 31;
    if (i >= n) return;
    float s1i = g_s1o[i];
    float4 acc0 = make_float4(0.f, 0.f, 0.f, 0.f);
    float4 acc1 = make_float4(0.f, 0.f, 0.f, 0.f);
    float rs = 0.0f;
    int pb = g_rowptr[i], pe = g_rowptr[i + 1];
    int j = (pb < pe) ? g_col[pb] : 0;
    float s2j = (pb < pe) ? g_s2o[j] : 0.0f;
    for (int p = pb; p < pe; p++) {
        int jn = (p + 1 < pe) ? g_col[p + 1] : 0;
        float sc = s1i + s2j;
        float t = (sc >= 0.0f) ? sc : 0.2f * sc;
        float e = __expf(-t);
        rs += e;
        const float4* hr = (const float4*)(g_h1 + (size_t)j * DCAT);  // layer2 h
        float4 v0 = hr[lane];
        float4 v1 = hr[lane + 32];
        float s2n = (p + 1 < pe) ? g_s2o[jn] : 0.0f;   // prefetch next score
        acc0.x = fmaf(e, v0.x, acc0.x); acc0.y = fmaf(e, v0.y, acc0.y);
        acc0.z = fmaf(e, v0.z, acc0.z); acc0.w = fmaf(e, v0.w, acc0.w);
        acc1.x = fmaf(e, v1.x, acc1.x); acc1.y = fmaf(e, v1.y, acc1.y);
        acc1.z = fmaf(e, v1.z, acc1.z); acc1.w = fmaf(e, v1.w, acc1.w);
        j = jn; s2j = s2n;
    }
    float inv = 1.0f / (rs + 1e-16f);
    float4 o0 = make_float4(elu1(acc0.x * inv), elu1(acc0.y * inv),
                            elu1(acc0.z * inv), elu1(acc0.w * inv));
    float4 o1 = make_float4(elu1(acc1.x * inv), elu1(acc1.y * inv),
                            elu1(acc1.z * inv), elu1(acc1.w * inv));
    float4* orow = (float4*)(out + (size_t)i * DCAT);
    orow[lane] = o0;
    orow[lane + 32] = o1;
}

// ---------------- launch ----------------
extern "C" void kernel_launch(void* const* d_in, const int* in_sizes, int n_in,
                              void* d_out, int out_size) {
    const float* x       = (const float*)d_in[0];
    const int*   edges   = (const int*)d_in[1];
    const float* W_heads = (const float*)d_in[2];
    const float* a_heads = (const float*)d_in[3];
    const float* W_out   = (const float*)d_in[4];
    const float* a_out   = (const float*)d_in[5];
    float* out = (float*)d_out;

    int N = in_sizes[0] / NFEAT;
    int E = in_sizes[1] / 2;
    if (N > MAXN) N = MAXN;
    if (E > MAXE) E = MAXE;
    const int* src = edges;
    const int* dst = edges + E;

    void *p_h1, *p_x2, *p_Wcat;
    cudaGetSymbolAddress(&p_h1, g_h1);
    cudaGetSymbolAddress(&p_x2, g_x2);
    cudaGetSymbolAddress(&p_Wcat, g_Wcat);

    int warpBlocks = (N * 32 + 255) / 256;
    int nb = (N + 1023) / 1024;

    // Launch order engineered so sgemm1 is the 4th launch (profiler's fixed
    // skip window captured launch idx 3 last round -> capture the GEMM now).
    zero_k<<<(N + 255) / 256, 256>>>(N);                                   // 0
    pack_w<<<(NHEADS * NFEAT * NHID + 255) / 256, 256>>>(W_heads);         // 1
    count_k<<<(E + 255) / 256, 256>>>(src, E);                             // 2
    sgemm128<<<dim3(DCAT / 128, (N + 127) / 128), 256>>>(                  // 3
        x, (const float*)p_Wcat, (float*)p_h1, N, DCAT, NFEAT);
    scan_block<<<nb, 1024>>>(N);                                           // 4
    scan_part<<<1, 32>>>(nb, N);                                           // 5
    scan_add<<<(N + 255) / 256, 256>>>(N);                                 // 6
    scatter_k<<<(E + 255) / 256, 256>>>(src, dst, E);                      // 7
    score_l1<<<warpBlocks, 256>>>(a_heads, N);                             // 8
    agg1<<<warpBlocks, 256>>>(N);                                          // 9

    // Layer 2 (h2 reuses g_h1)
    sgemm128<<<dim3(DCAT / 128, (N + 127) / 128), 256>>>(                  // 10
        (const float*)p_x2, W_out, (float*)p_h1, N, DCAT, DCAT);
    score_l2<<<warpBlocks, 256>>>(a_out, N);                               // 11
    agg2<<<warpBlocks, 256>>>(out, N);                                     // 12
}

// round 8
// speedup vs baseline: 1.3399x; 1.2975x over previous
#include <cuda_runtime.h>
#include <cuda_bf16.h>
#include <math.h>
#include <stdint.h>

#define MAXN 100000
#define MAXE 1600000
#define NHID 32
#define NHEADS 8
#define DCAT 256   /* NHEADS*NHID */
#define NFEAT 128

// ---------------- scratch (device globals; no allocation allowed) ----------------
__device__ float g_h1[(size_t)MAXN * DCAT];   // layer1 h, then layer2 h (aliased)
__device__ float g_x2[(size_t)MAXN * DCAT];   // layer1 output (post elu)
__device__ float g_s1[MAXN * NHEADS];
__device__ float g_s2[MAXN * NHEADS];
__device__ float g_s1o[MAXN];
__device__ float g_s2o[MAXN];
__device__ float g_WT1[DCAT * NFEAT];         // layer1 weights as [N=256, K=128]
__device__ float g_WT2[DCAT * DCAT];          // layer2 weights as [N=256, K=256]
__device__ int   g_rowptr[MAXN + 1];
__device__ int   g_cursor[MAXN];
__device__ int   g_col[MAXE];
__device__ int   g_partials[128];
__device__ int   g_poff[128];

// ---------------- small helpers ----------------
__device__ __forceinline__ float warp_sum(float v) {
    #pragma unroll
    for (int o = 16; o; o >>= 1) v += __shfl_xor_sync(0xffffffffu, v, o);
    return v;
}
__device__ __forceinline__ float elu1(float v) { return v > 0.0f ? v : expm1f(v); }

__device__ __forceinline__ uint32_t smem_u32(const void* p) {
    uint32_t a;
    asm("{ .reg .u64 t; cvta.to.shared.u64 t, %1; cvt.u32.u64 %0, t; }" : "=r"(a) : "l"(p));
    return a;
}

// pack two floats -> bf16x2 (low = first arg)
__device__ __forceinline__ uint32_t bfpack(float x, float y) {
    __nv_bfloat162 h2 = __floats2bfloat162_rn(x, y);
    return *reinterpret_cast<uint32_t*>(&h2);
}

__device__ __forceinline__ void ldmx4(uint32_t* r, uint32_t addr) {
    asm volatile("ldmatrix.sync.aligned.m8n8.x4.shared.b16 {%0,%1,%2,%3}, [%4];"
        : "=r"(r[0]), "=r"(r[1]), "=r"(r[2]), "=r"(r[3]) : "r"(addr));
}
__device__ __forceinline__ void ldmx2(uint32_t* r, uint32_t addr) {
    asm volatile("ldmatrix.sync.aligned.m8n8.x2.shared.b16 {%0,%1}, [%2];"
        : "=r"(r[0]), "=r"(r[1]) : "r"(addr));
}
__device__ __forceinline__ void mma_bf16(float* d, const uint32_t* a, const uint32_t* b) {
    asm volatile(
        "mma.sync.aligned.m16n8k16.row.col.f32.bf16.bf16.f32 "
        "{%0,%1,%2,%3}, {%4,%5,%6,%7}, {%8,%9}, {%10,%11,%12,%13};"
        : "=f"(d[0]), "=f"(d[1]), "=f"(d[2]), "=f"(d[3])
        : "r"(a[0]), "r"(a[1]), "r"(a[2]), "r"(a[3]), "r"(b[0]), "r"(b[1]),
          "f"(d[0]), "f"(d[1]), "f"(d[2]), "f"(d[3]));
}

// ---------------- CSR build ----------------
__global__ void zero_k(int n) {
    int i = blockIdx.x * blockDim.x + threadIdx.x;
    if (i < n) g_cursor[i] = 0;
}
__global__ void pack_wt1(const float* __restrict__ W_heads) {
    // W_heads [8,128,32] -> WT1 [n=32h+c][k] = W_heads[h][k][c]
    int idx = blockIdx.x * blockDim.x + threadIdx.x;
    if (idx < NHEADS * NFEAT * NHID) {
        int h = idx / (NFEAT * NHID);
        int k = (idx / NHID) % NFEAT;
        int c = idx % NHID;
        g_WT1[(h * NHID + c) * NFEAT + k] = W_heads[idx];
    }
}
__global__ void pack_wt2(const float* __restrict__ W_out) {
    // W_out [k][n] -> WT2 [n][k]
    int idx = blockIdx.x * blockDim.x + threadIdx.x;
    if (idx < DCAT * DCAT) {
        int k = idx >> 8, n = idx & 255;
        g_WT2[n * DCAT + k] = W_out[idx];
    }
}
__global__ void count_k(const int* __restrict__ src, int E) {
    int e = blockIdx.x * blockDim.x + threadIdx.x;
    if (e < E) atomicAdd(&g_cursor[src[e]], 1);
}
__global__ void scan_block(int n) {
    __shared__ int sh[1024];
    int gid = blockIdx.x * 1024 + threadIdx.x;
    int v = (gid < n) ? g_cursor[gid] : 0;
    sh[threadIdx.x] = v;
    __syncthreads();
    #pragma unroll
    for (int off = 1; off < 1024; off <<= 1) {
        int t = 0;
        if (threadIdx.x >= off) t = sh[threadIdx.x - off];
        __syncthreads();
        if (threadIdx.x >= off) sh[threadIdx.x] += t;
        __syncthreads();
    }
    if (gid < n) g_rowptr[gid] = sh[threadIdx.x] - v;
    if (threadIdx.x == 1023) g_partials[blockIdx.x] = sh[1023];
}
__global__ void scan_part(int nb, int n) {
    if (threadIdx.x == 0 && blockIdx.x == 0) {
        int acc = 0;
        for (int b = 0; b < nb; b++) { g_poff[b] = acc; acc += g_partials[b]; }
        g_rowptr[n] = acc;
    }
}
__global__ void scan_add(int n) {
    int gid = blockIdx.x * blockDim.x + threadIdx.x;
    if (gid < n) {
        int v = g_rowptr[gid] + g_poff[gid >> 10];
        g_rowptr[gid] = v;
        g_cursor[gid] = v;
    }
}
__global__ void scatter_k(const int* __restrict__ src, const int* __restrict__ dst, int E) {
    int e = blockIdx.x * blockDim.x + threadIdx.x;
    if (e < E) {
        int p = atomicAdd(&g_cursor[src[e]], 1);
        g_col[p] = dst[e];
    }
}

// ---------------- bf16-split mma.sync GEMM: C[M,256] = A[M,K] @ BT[256,K]^T ----------------
// 2-way split: A=Ah+Al, B=Bh+Bl; D = Ah*Bh + Ah*Bl + Al*Bh (drop Al*Bl ~2^-18)
#define PITCH 20   /* u32 per 32-float row; 20i mod 32 spans all banks */

__global__ __launch_bounds__(256) void bf16_gemm(
    const float* __restrict__ A, const float* __restrict__ BT,
    float* __restrict__ C, int M, int K) {
    __shared__ uint32_t sAh[128 * PITCH], sAl[128 * PITCH];
    __shared__ uint32_t sBh[128 * PITCH], sBl[128 * PITCH];

    const int tid = threadIdx.x, wid = tid >> 5, lane = tid & 31;
    const int rowBase = blockIdx.y * 128;
    const int colBase = blockIdx.x * 128;
    const int warpM = (wid & 1) * 64;
    const int warpN = (wid >> 1) * 32;
    const int g = lane >> 2, t4 = lane & 3;

    float acc[4][4][4];
    #pragma unroll
    for (int mt = 0; mt < 4; mt++)
        #pragma unroll
        for (int nt = 0; nt < 4; nt++)
            #pragma unroll
            for (int q = 0; q < 4; q++) acc[mt][nt][q] = 0.0f;

    // ldmatrix per-lane addresses (byte offsets into the 4 smem arrays)
    uint32_t bAh = smem_u32(sAh), bAl = smem_u32(sAl);
    uint32_t bBh = smem_u32(sBh), bBl = smem_u32(sBl);
    // A x4: lanes 0-15 -> rows m0..15 (k lo 8x8 pair), lanes 16-31 same rows k hi
    uint32_t aoff = ((uint32_t)(warpM + (lane & 15)) * PITCH + (lane >> 4) * 4) * 4;
    // B x2: lanes 0-7 -> n rows k lo, lanes 8-15 -> k hi
    uint32_t boff = ((uint32_t)(warpN + (lane & 7)) * PITCH + ((lane >> 3) & 1) * 4) * 4;

    const int NC = K >> 5;
    for (int kc = 0; kc < NC; kc++) {
        __syncthreads();
        // fill: A tile 128x32, B tile 128x32 (4 float4 each per thread)
        #pragma unroll
        for (int t = 0; t < 4; t++) {
            int idx = tid + t * 256;
            int r = idx >> 3, c4 = idx & 7;
            // ---- A ----
            float4 v = make_float4(0.f, 0.f, 0.f, 0.f);
            int gr = rowBase + r;
            if (gr < M) v = *(const float4*)(A + (size_t)gr * K + kc * 32 + c4 * 4);
            uint32_t p0 = bfpack(v.x, v.y);
            uint32_t p1 = bfpack(v.z, v.w);
            float4 lo;
            lo.x = v.x - __uint_as_float(p0 << 16);
            lo.y = v.y - __uint_as_float(p0 & 0xffff0000u);
            lo.z = v.z - __uint_as_float(p1 << 16);
            lo.w = v.w - __uint_as_float(p1 & 0xffff0000u);
            int so = r * PITCH + c4 * 2;
            sAh[so] = p0; sAh[so + 1] = p1;
            sAl[so] = bfpack(lo.x, lo.y); sAl[so + 1] = bfpack(lo.z, lo.w);
            // ---- B ----
            float4 w = *(const float4*)(BT + (size_t)(colBase + r) * K + kc * 32 + c4 * 4);
            uint32_t q0 = bfpack(w.x, w.y);
            uint32_t q1 = bfpack(w.z, w.w);
            float4 wl;
            wl.x = w.x - __uint_as_float(q0 << 16);
            wl.y = w.y - __uint_as_float(q0 & 0xffff0000u);
            wl.z = w.z - __uint_as_float(q1 << 16);
            wl.w = w.w - __uint_as_float(q1 & 0xffff0000u);
            sBh[so] = q0; sBh[so + 1] = q1;
            sBl[so] = bfpack(wl.x, wl.y); sBl[so + 1] = bfpack(wl.z, wl.w);
        }
        __syncthreads();

        #pragma unroll
        for (int ks = 0; ks < 2; ks++) {
            uint32_t ko = (uint32_t)(ks * 32);   // 8 u32 = 32 bytes per k16 step
            uint32_t Ah[4][4], Al[4][4], Bh[4][2], Bl[4][2];
            #pragma unroll
            for (int mt = 0; mt < 4; mt++) {
                uint32_t ro = (uint32_t)(mt * 16 * PITCH * 4);
                ldmx4(Ah[mt], bAh + aoff + ro + ko);
                ldmx4(Al[mt], bAl + aoff + ro + ko);
            }
            #pragma unroll
            for (int nt = 0; nt < 4; nt++) {
                uint32_t no = (uint32_t)(nt * 8 * PITCH * 4);
                ldmx2(Bh[nt], bBh + boff + no + ko);
                ldmx2(Bl[nt], bBl + boff + no + ko);
            }
            #pragma unroll
            for (int mt = 0; mt < 4; mt++)
                #pragma unroll
                for (int nt = 0; nt < 4; nt++)
                    mma_bf16(acc[mt][nt], Ah[mt], Bh[nt]);
            #pragma unroll
            for (int mt = 0; mt < 4; mt++)
                #pragma unroll
                for (int nt = 0; nt < 4; nt++)
                    mma_bf16(acc[mt][nt], Ah[mt], Bl[nt]);
            #pragma unroll
            for (int mt = 0; mt < 4; mt++)
                #pragma unroll
                for (int nt = 0; nt < 4; nt++)
                    mma_bf16(acc[mt][nt], Al[mt], Bh[nt]);
        }
    }

    // epilogue
    #pragma unroll
    for (int mt = 0; mt < 4; mt++) {
        int row0 = rowBase + warpM + mt * 16 + g;
        int row1 = row0 + 8;
        #pragma unroll
        for (int nt = 0; nt < 4; nt++) {
            int col = colBase + warpN + nt * 8 + t4 * 2;
            if (row0 < M)
                *(float2*)(C + (size_t)row0 * DCAT + col) =
                    make_float2(acc[mt][nt][0], acc[mt][nt][1]);
            if (row1 < M)
                *(float2*)(C + (size_t)row1 * DCAT + col) =
                    make_float2(acc[mt][nt][2], acc[mt][nt][3]);
        }
    }
}

// ---------------- per-node scores ----------------
__global__ void score_l1(const float* __restrict__ a_heads, int n) {
    int i = (blockIdx.x * blockDim.x + threadIdx.x) >> 5;
    int lane = threadIdx.x & 31;
    if (i >= n) return;
    const float* hrow = g_h1 + (size_t)i * DCAT;
    #pragma unroll
    for (int h = 0; h < NHEADS; h++) {
        float hv = hrow[h * NHID + lane];
        float p1 = hv * a_heads[h * 64 + lane];
        float p2 = hv * a_heads[h * 64 + 32 + lane];
        p1 = warp_sum(p1);
        p2 = warp_sum(p2);
        if (lane == 0) {
            g_s1[i * NHEADS + h] = p1;
            g_s2[i * NHEADS + h] = p2;
        }
    }
}

__global__ void score_l2(const float* __restrict__ a_out, int n) {
    int i = (blockIdx.x * blockDim.x + threadIdx.x) >> 5;
    int lane = threadIdx.x & 31;
    if (i >= n) return;
    const float* hrow = g_h1 + (size_t)i * DCAT;   // layer2 h lives in g_h1
    float p1 = 0.f, p2 = 0.f;
    #pragma unroll
    for (int k = 0; k < 8; k++) {
        float hv = hrow[k * 32 + lane];
        p1 = fmaf(hv, a_out[k * 32 + lane], p1);
        p2 = fmaf(hv, a_out[256 + k * 32 + lane], p2);
    }
    p1 = warp_sum(p1);
    p2 = warp_sum(p2);
    if (lane == 0) { g_s1o[i] = p1; g_s2o[i] = p2; }
}

// ---------------- aggregation: warp per node, float4 gathers ----------------
__global__ void agg1(int n) {
    int i = (blockIdx.x * blockDim.x + threadIdx.x) >> 5;
    int lane = threadIdx.x & 31;
    if (i >= n) return;
    float s1h = (lane < NHEADS) ? g_s1[i * NHEADS + lane] : 0.0f;
    const int h0 = lane >> 3, h1 = 4 + (lane >> 3);
    float4 acc0 = make_float4(0.f, 0.f, 0.f, 0.f);
    float4 acc1 = make_float4(0.f, 0.f, 0.f, 0.f);
    float rs = 0.0f;
    int pb = g_rowptr[i], pe = g_rowptr[i + 1];
    int j = (pb < pe) ? g_col[pb] : 0;
    for (int p = pb; p < pe; p++) {
        int jn = (p + 1 < pe) ? g_col[p + 1] : 0;
        float eh = 0.0f;
        if (lane < NHEADS) {
            float sc = s1h + g_s2[j * NHEADS + lane];
            float t = (sc >= 0.0f) ? sc : 0.2f * sc;
            eh = __expf(-t);
            rs += eh;
        }
        const float4* hr = (const float4*)(g_h1 + (size_t)j * DCAT);
        float4 v0 = hr[lane];
        float4 v1 = hr[lane + 32];
        float e0 = __shfl_sync(0xffffffffu, eh, h0);
        float e1 = __shfl_sync(0xffffffffu, eh, h1);
        acc0.x = fmaf(e0, v0.x, acc0.x); acc0.y = fmaf(e0, v0.y, acc0.y);
        acc0.z = fmaf(e0, v0.z, acc0.z); acc0.w = fmaf(e0, v0.w, acc0.w);
        acc1.x = fmaf(e1, v1.x, acc1.x); acc1.y = fmaf(e1, v1.y, acc1.y);
        acc1.z = fmaf(e1, v1.z, acc1.z); acc1.w = fmaf(e1, v1.w, acc1.w);
        j = jn;
    }
    float r0 = __shfl_sync(0xffffffffu, rs, h0) + 1e-16f;
    float r1 = __shfl_sync(0xffffffffu, rs, h1) + 1e-16f;
    float inv0 = 1.0f / r0, inv1 = 1.0f / r1;
    float4 o0 = make_float4(elu1(acc0.x * inv0), elu1(acc0.y * inv0),
                            elu1(acc0.z * inv0), elu1(acc0.w * inv0));
    float4 o1 = make_float4(elu1(acc1.x * inv1), elu1(acc1.y * inv1),
                            elu1(acc1.z * inv1), elu1(acc1.w * inv1));
    float4* xout = (float4*)(g_x2 + (size_t)i * DCAT);
    xout[lane] = o0;
    xout[lane + 32] = o1;
}

__global__ void agg2(float* __restrict__ out, int n) {
    int i = (blockIdx.x * blockDim.x + threadIdx.x) >> 5;
    int lane = threadIdx.x & 31;
    if (i >= n) return;
    float s1i = g_s1o[i];
    float4 acc0 = make_float4(0.f, 0.f, 0.f, 0.f);
    float4 acc1 = make_float4(0.f, 0.f, 0.f, 0.f);
    float rs = 0.0f;
    int pb = g_rowptr[i], pe = g_rowptr[i + 1];
    int j = (pb < pe) ? g_col[pb] : 0;
    float s2j = (pb < pe) ? g_s2o[j] : 0.0f;
    for (int p = pb; p < pe; p++) {
        int jn = (p + 1 < pe) ? g_col[p + 1] : 0;
        float sc = s1i + s2j;
        float t = (sc >= 0.0f) ? sc : 0.2f * sc;
        float e = __expf(-t);
        rs += e;
        const float4* hr = (const float4*)(g_h1 + (size_t)j * DCAT);
        float4 v0 = hr[lane];
        float4 v1 = hr[lane + 32];
        float s2n = (p + 1 < pe) ? g_s2o[jn] : 0.0f;
        acc0.x = fmaf(e, v0.x, acc0.x); acc0.y = fmaf(e, v0.y, acc0.y);
        acc0.z = fmaf(e, v0.z, acc0.z); acc0.w = fmaf(e, v0.w, acc0.w);
        acc1.x = fmaf(e, v1.x, acc1.x); acc1.y = fmaf(e, v1.y, acc1.y);
        acc1.z = fmaf(e, v1.z, acc1.z); acc1.w = fmaf(e, v1.w, acc1.w);
        j = jn; s2j = s2n;
    }
    float inv = 1.0f / (rs + 1e-16f);
    float4 o0 = make_float4(elu1(acc0.x * inv), elu1(acc0.y * inv),
                            elu1(acc0.z * inv), elu1(acc0.w * inv));
    float4 o1 = make_float4(elu1(acc1.x * inv), elu1(acc1.y * inv),
                            elu1(acc1.z * inv), elu1(acc1.w * inv));
    float4* orow = (float4*)(out + (size_t)i * DCAT);
    orow[lane] = o0;
    orow[lane + 32] = o1;
}

// ---------------- launch ----------------
extern "C" void kernel_launch(void* const* d_in, const int* in_sizes, int n_in,
                              void* d_out, int out_size) {
    const float* x       = (const float*)d_in[0];
    const int*   edges   = (const int*)d_in[1];
    const float* W_heads = (const float*)d_in[2];
    const float* a_heads = (const float*)d_in[3];
    const float* W_out   = (const float*)d_in[4];
    const float* a_out   = (const float*)d_in[5];
    float* out = (float*)d_out;

    int N = in_sizes[0] / NFEAT;
    int E = in_sizes[1] / 2;
    if (N > MAXN) N = MAXN;
    if (E > MAXE) E = MAXE;
    const int* src = edges;
    const int* dst = edges + E;

    void *p_h1, *p_x2, *p_WT1, *p_WT2;
    cudaGetSymbolAddress(&p_h1, g_h1);
    cudaGetSymbolAddress(&p_x2, g_x2);
    cudaGetSymbolAddress(&p_WT1, g_WT1);
    cudaGetSymbolAddress(&p_WT2, g_WT2);

    int warpBlocks = (N * 32 + 255) / 256;
    int nb = (N + 1023) / 1024;
    dim3 gemmGrid(DCAT / 128, (N + 127) / 128);

    zero_k<<<(N + 255) / 256, 256>>>(N);                                   // 0
    pack_wt1<<<(NHEADS * NFEAT * NHID + 255) / 256, 256>>>(W_heads);       // 1
    count_k<<<(E + 255) / 256, 256>>>(src, E);                             // 2
    bf16_gemm<<<gemmGrid, 256>>>(                                          // 3 (profiled)
        x, (const float*)p_WT1, (float*)p_h1, N, NFEAT);
    scan_block<<<nb, 1024>>>(N);                                           // 4
    scan_part<<<1, 32>>>(nb, N);                                           // 5
    scan_add<<<(N + 255) / 256, 256>>>(N);                                 // 6
    scatter_k<<<(E + 255) / 256, 256>>>(src, dst, E);                      // 7
    score_l1<<<warpBlocks, 256>>>(a_heads, N);                             // 8
    agg1<<<warpBlocks, 256>>>(N);                                          // 9

    // Layer 2 (h2 reuses g_h1)
    pack_wt2<<<(DCAT * DCAT + 255) / 256, 256>>>(W_out);                   // 10
    bf16_gemm<<<gemmGrid, 256>>>(                                          // 11
        (const float*)p_x2, (const float*)p_WT2, (float*)p_h1, N, DCAT);
    score_l2<<<warpBlocks, 256>>>(a_out, N);                               // 12
    agg2<<<warpBlocks, 256>>>(out, N);                                     // 13
}